// round 6
// baseline (speedup 1.0000x reference)
#include <cuda_runtime.h>

#define NCLS    19
#define NBINS   15
#define HW      (512 * 1024)          // 2^19
#define NPIX    (4 * HW)              // 2,097,152
#define NPAIR   (NPIX / 2)            // 1,048,576
#define NCELLS  (NCLS * NBINS)        // 285
#define NT      256
#define GRIDB   740                   // 5 blocks/SM guaranteed resident
#define PPB     (NT / 4)              // 64 pixel-pairs per block-iteration
#define STRIDE  (GRIDB * PPB)

// g_hist[c*15+b] = sum of 15*(p - [label==c]) over pixels with bin(p_c)=b.
// sce = sum(|g_hist|) / (15*C*N).  Invariant: zero at entry; last block resets.
__device__ float    g_hist[NCELLS];
__device__ unsigned g_count;

__global__ __launch_bounds__(NT, 5)
void ece_fused(const float* __restrict__ logits,
               const int*   __restrict__ labels,
               float*       __restrict__ out) {
    __shared__ float s_hist[NCELLS];
    __shared__ bool  s_last;
    for (int i = threadIdx.x; i < NCELLS; i += NT) s_hist[i] = 0.f;
    __syncthreads();

    const unsigned sbase = (unsigned)__cvta_generic_to_shared(s_hist);
    const int g  = threadIdx.x & 3;          // class group within pixel quad
    const int q  = threadIdx.x >> 2;         // pair slot within block
    const int c0 = g * 5;                    // first owned class (g=3 owns 4)

    // Register bin 0 only: a0[i] = sum of v over values with t <= 1 (~77%).
    // All t > 1 go through a branch-free predicated red.shared below.
    float a0[5];
#pragma unroll
    for (int i = 0; i < 5; i++) a0[i] = 0.f;

    for (unsigned pp = blockIdx.x * PPB + q; pp < NPAIR; pp += STRIDE) {
        const unsigned p  = pp << 1;
        const unsigned b  = p >> 19;
        const unsigned hw = p & (HW - 1);
        const float* row  = logits + (size_t)b * (NCLS * HW) + hw;
        const int2 lb = __ldg((const int2*)labels + pp);

        float2 e[5];
#pragma unroll
        for (int i = 0; i < 5; i++) {
            const int c = c0 + i;
            // dead slot (c==19): exp(-100) flushes to 0 -> contributes nothing
            e[i] = (c < NCLS) ? __ldg((const float2*)(row + (size_t)c * HW))
                              : make_float2(-100.f, -100.f);
        }
        float Sx = 0.f, Sy = 0.f;
#pragma unroll
        for (int i = 0; i < 5; i++) {
            e[i].x = __expf(e[i].x); Sx += e[i].x;
            e[i].y = __expf(e[i].y); Sy += e[i].y;
        }
        // Softmax denominator across the 4-lane quad.
        Sx += __shfl_xor_sync(~0u, Sx, 1);  Sy += __shfl_xor_sync(~0u, Sy, 1);
        Sx += __shfl_xor_sync(~0u, Sx, 2);  Sy += __shfl_xor_sync(~0u, Sy, 2);
        const float wx = __fdividef(15.f, Sx);
        const float wy = __fdividef(15.f, Sy);

#pragma unroll
        for (int i = 0; i < 5; i++) {
            const int c = c0 + i;
            {   // pixel 0 of the pair
                const float t = e[i].x * wx;                 // 15*p
                const float v = (c == lb.x) ? t - 15.f : t;  // 15*(p - eq)
                if (t <= 1.f) a0[i] += v;
                // cell = c*15 + (min(ceil(t),15) - 1); valid even when unused
                const unsigned addr = sbase +
                    (unsigned)((c * NBINS - 1 + min(__float2int_ru(t), NBINS)) << 2);
                // branch-free: predicated shared reduction, no BSSY/BSYNC
                asm volatile(
                    "{ .reg .pred p; setp.gt.f32 p, %1, 0f3F800000;\n\t"
                    "  @p red.shared.add.f32 [%0], %2; }"
                    :: "r"(addr), "f"(t), "f"(v) : "memory");
            }
            {   // pixel 1 of the pair
                const float t = e[i].y * wy;
                const float v = (c == lb.y) ? t - 15.f : t;
                if (t <= 1.f) a0[i] += v;
                const unsigned addr = sbase +
                    (unsigned)((c * NBINS - 1 + min(__float2int_ru(t), NBINS)) << 2);
                asm volatile(
                    "{ .reg .pred p; setp.gt.f32 p, %1, 0f3F800000;\n\t"
                    "  @p red.shared.add.f32 [%0], %2; }"
                    :: "r"(addr), "f"(t), "f"(v) : "memory");
            }
        }
    }

    // Reduce a0 across the 8 lanes sharing each class (xor over bits 2..4).
    const int lane = threadIdx.x & 31;
#pragma unroll
    for (int i = 0; i < 5; i++) {
        float x = a0[i];
#pragma unroll
        for (int s = 4; s < 32; s <<= 1) x += __shfl_xor_sync(~0u, x, s);
        if (lane < 4 && c0 + i < NCLS)            // lane == its own group id
            atomicAdd(&s_hist[(c0 + i) * NBINS + 0], x);
    }
    __syncthreads();

    for (int i = threadIdx.x; i < NCELLS; i += NT) {
        const float v = s_hist[i];
        if (v != 0.f) atomicAdd(&g_hist[i], v);
    }

    // Completion protocol; last block finalizes and restores invariants.
    __threadfence();
    __syncthreads();
    if (threadIdx.x == 0) {
        const unsigned r = atomicInc(&g_count, GRIDB - 1);   // wraps back to 0
        s_last = (r == GRIDB - 1);
    }
    __syncthreads();

    if (s_last && threadIdx.x < 32) {
        __threadfence();
        double local = 0.0;
        for (int i = lane; i < NCELLS; i += 32) {
            local += fabs((double)g_hist[i]);
            g_hist[i] = 0.f;
        }
#pragma unroll
        for (int s = 16; s > 0; s >>= 1)
            local += __shfl_xor_sync(~0u, local, s);
        if (lane == 0)
            out[0] = (float)(local / (15.0 * (double)NCLS * (double)NPIX));
    }
}

extern "C" void kernel_launch(void* const* d_in, const int* in_sizes, int n_in,
                              void* d_out, int out_size) {
    const float* logits;
    const int*   labels;
    if (in_sizes[0] == NPIX) {               // defensive order detection by size
        labels = (const int*)d_in[0];
        logits = (const float*)d_in[1];
    } else {
        logits = (const float*)d_in[0];
        labels = (const int*)d_in[1];
    }
    float* out = (float*)d_out;

    ece_fused<<<GRIDB, NT>>>(logits, labels, out);
}

// round 9
// speedup vs baseline: 1.0477x; 1.0477x over previous
#include <cuda_runtime.h>

#define NCLS    19
#define NBINS   15
#define HW      (512 * 1024)          // 2^19 pixels per image
#define NPIX    (4 * HW)              // 2,097,152
#define HPAIR   (HW / 2)              // pairs per image
#define NCELLS  (NCLS * NBINS)        // 285
#define NT      256
#define GX      148                   // blocks per image (1 wave, 4/SM, no tail)
#define GRIDB   (GX * 4)              // 592
#define PPB     (NT / 4)              // 64 pairs per block-iteration
#define STRIDE  (GX * PPB)            // 9472 pairs

// g_hist[c*15+b] = sum of 15*(p - [label==c]) over pixels with bin(p_c)=b.
// sce = sum(|g_hist|) / (15*C*N).  Invariant: zero at entry; last block resets.
__device__ float    g_hist[NCELLS];
__device__ unsigned g_count;

__global__ __launch_bounds__(NT, 4)
void ece_fused(const float* __restrict__ logits,
               const int*   __restrict__ labels,
               float*       __restrict__ out) {
    __shared__ float s_hist[NCELLS];    // bins >= 2 receive rare reds only
    __shared__ float s_b0[NCLS];        // per-class sum over t<=1
    __shared__ float s_tot[NCLS];       // per-class total sum
    __shared__ bool  s_last;
    for (int i = threadIdx.x; i < NCELLS; i += NT) s_hist[i] = 0.f;
    if (threadIdx.x < NCLS) { s_b0[threadIdx.x] = 0.f; s_tot[threadIdx.x] = 0.f; }
    __syncthreads();

    const unsigned sbase = (unsigned)__cvta_generic_to_shared(s_hist);
    const int g  = threadIdx.x & 3;          // class group within pixel quad
    const int q  = threadIdx.x >> 2;         // pair slot within block
    const int c0 = g * 5;                    // first owned class (g=3 owns 4)

    const float* imgbase = logits + (size_t)blockIdx.y * (NCLS * HW);
    const int*   labbase = labels + (size_t)blockIdx.y * HW;

    float a0[5], atot[5];
#pragma unroll
    for (int i = 0; i < 5; i++) { a0[i] = 0.f; atot[i] = 0.f; }

    for (unsigned pp = blockIdx.x * PPB + q; pp < HPAIR; pp += STRIDE) {
        const float* row = imgbase + (pp << 1);
        const int2 lb = __ldg((const int2*)labbase + pp);

        float2 e[5];
#pragma unroll
        for (int i = 0; i < 5; i++) {
            const int c = c0 + i;
            // dead slot (c==19): exp(-100)=0 contributes nothing anywhere
            e[i] = (c < NCLS) ? __ldg((const float2*)(row + (size_t)c * HW))
                              : make_float2(-100.f, -100.f);
        }
        float Sx = 0.f, Sy = 0.f;
#pragma unroll
        for (int i = 0; i < 5; i++) {
            e[i].x = __expf(e[i].x); Sx += e[i].x;
            e[i].y = __expf(e[i].y); Sy += e[i].y;
        }
        Sx += __shfl_xor_sync(~0u, Sx, 1);  Sy += __shfl_xor_sync(~0u, Sy, 1);
        Sx += __shfl_xor_sync(~0u, Sx, 2);  Sy += __shfl_xor_sync(~0u, Sy, 2);
        const float wx = __fdividef(15.f, Sx);
        const float wy = __fdividef(15.f, Sy);

#pragma unroll
        for (int i = 0; i < 5; i++) {
            const int c = c0 + i;
            const unsigned cellbase = sbase + (unsigned)((c * NBINS - 1) << 2);
            {   // pixel 0
                const float t = e[i].x * wx;                 // 15*p
                const float v = (c == lb.x) ? t - 15.f : t;  // 15*(p - eq)
                atot[i] += v;
                if (t <= 1.f) a0[i] += v;
                const unsigned addr =
                    cellbase + (unsigned)(min(__float2int_ru(t), NBINS) << 2);
                asm volatile(                                // branch-free rare path
                    "{ .reg .pred p; setp.gt.f32 p, %1, 0f40000000;\n\t" // t > 2
                    "  @p red.shared.add.f32 [%0], %2; }"
                    :: "r"(addr), "f"(t), "f"(v) : "memory");
            }
            {   // pixel 1
                const float t = e[i].y * wy;
                const float v = (c == lb.y) ? t - 15.f : t;
                atot[i] += v;
                if (t <= 1.f) a0[i] += v;
                const unsigned addr =
                    cellbase + (unsigned)(min(__float2int_ru(t), NBINS) << 2);
                asm volatile(
                    "{ .reg .pred p; setp.gt.f32 p, %1, 0f40000000;\n\t"
                    "  @p red.shared.add.f32 [%0], %2; }"
                    :: "r"(addr), "f"(t), "f"(v) : "memory");
            }
        }
    }

    // Reduce across the 8 lanes sharing each class (xor over lane bits 2..4).
    const int lane = threadIdx.x & 31;
#pragma unroll
    for (int i = 0; i < 5; i++) {
        float x0 = atot[i], x1 = a0[i];
#pragma unroll
        for (int s = 4; s < 32; s <<= 1) {
            x0 += __shfl_xor_sync(~0u, x0, s);
            x1 += __shfl_xor_sync(~0u, x1, s);
        }
        if (lane < 4 && c0 + i < NCLS) {          // lane == its own group id
            atomicAdd(&s_tot[c0 + i], x0);
            atomicAdd(&s_b0[c0 + i],  x1);
        }
    }
    __syncthreads();

    // Flush: bin0 = b0, bin1 = tot - b0 - rare, bins>=2 = rare cells.
    for (int c = threadIdx.x; c < NCLS; c += NT) {
        float rare = 0.f;
#pragma unroll
        for (int b = 2; b < NBINS; b++) rare += s_hist[c * NBINS + b];
        atomicAdd(&g_hist[c * NBINS + 0], s_b0[c]);
        atomicAdd(&g_hist[c * NBINS + 1], s_tot[c] - s_b0[c] - rare);
#pragma unroll
        for (int b = 2; b < NBINS; b++) {
            const float v = s_hist[c * NBINS + b];
            if (v != 0.f) atomicAdd(&g_hist[c * NBINS + b], v);
        }
    }

    // Completion protocol; last block finalizes and restores invariants.
    __threadfence();
    __syncthreads();
    if (threadIdx.x == 0) {
        const unsigned r = atomicInc(&g_count, GRIDB - 1);   // wraps back to 0
        s_last = (r == GRIDB - 1);
    }
    __syncthreads();

    if (s_last && threadIdx.x < 32) {
        __threadfence();
        double local = 0.0;
        for (int i = lane; i < NCELLS; i += 32) {
            local += fabs((double)g_hist[i]);
            g_hist[i] = 0.f;
        }
#pragma unroll
        for (int s = 16; s > 0; s >>= 1)
            local += __shfl_xor_sync(~0u, local, s);
        if (lane == 0)
            out[0] = (float)(local / (15.0 * (double)NCLS * (double)NPIX));
    }
}

extern "C" void kernel_launch(void* const* d_in, const int* in_sizes, int n_in,
                              void* d_out, int out_size) {
    const float* logits;
    const int*   labels;
    if (in_sizes[0] == NPIX) {               // defensive order detection by size
        labels = (const int*)d_in[0];
        logits = (const float*)d_in[1];
    } else {
        logits = (const float*)d_in[0];
        labels = (const int*)d_in[1];
    }
    float* out = (float*)d_out;

    dim3 grid(GX, 4);
    ece_fused<<<grid, NT>>>(logits, labels, out);
}

// round 11
// speedup vs baseline: 1.0955x; 1.0457x over previous
#include <cuda_runtime.h>

#define NCLS    19
#define NBINS   15
#define HW      (512 * 1024)          // 2^19 pixels per image
#define NPIX    (4 * HW)              // 2,097,152
#define HPAIR   (HW / 2)              // 262,144 pairs per image
#define NCELLS  (NCLS * NBINS)        // 285
#define NT      512
#define GX      111                   // blocks per image; 111*4 = 444 = 3/SM
#define GRIDB   (GX * 4)
#define PPB     (NT / 4)              // 128 pairs per block-iteration
#define STRIDE  (GX * PPB)            // 14,208 pairs

// g_hist[c*15+b] = sum of 15*(p - [label==c]) over pixels with bin(p_c)=b.
// sce = sum(|g_hist|) / (15*C*N).  Invariant: zero at entry; last block resets.
__device__ float    g_hist[NCELLS];
__device__ unsigned g_count;

__global__ __launch_bounds__(NT, 3)
void ece_fused(const float* __restrict__ logits,
               const int*   __restrict__ labels,
               float*       __restrict__ out) {
    __shared__ float s_hist[NCELLS];   // rare t-sums, bins >= 2 only
    __shared__ float s_corr[NCELLS];   // label corrections (-15 events), any bin
    __shared__ float s_b0[NCLS];       // per-class sum of t over t<=1
    __shared__ float s_tot[NCLS];      // per-class total sum of t
    __shared__ bool  s_last;
    for (int i = threadIdx.x; i < NCELLS; i += NT) { s_hist[i] = 0.f; s_corr[i] = 0.f; }
    if (threadIdx.x < NCLS) { s_b0[threadIdx.x] = 0.f; s_tot[threadIdx.x] = 0.f; }
    __syncthreads();

    const int g  = threadIdx.x & 3;        // class group within pixel quad
    const int q  = threadIdx.x >> 2;       // pair slot within block
    const int c0 = g * 5;                  // first owned class (g=3 owns 4)

    const float* imgbase = logits + (size_t)blockIdx.y * (NCLS * HW);
    const int*   labbase = labels + (size_t)blockIdx.y * HW;

    float a0[5], atot[5];
#pragma unroll
    for (int i = 0; i < 5; i++) { a0[i] = 0.f; atot[i] = 0.f; }

    for (unsigned pp = blockIdx.x * PPB + q; pp < HPAIR; pp += STRIDE) {
        const float* row = imgbase + (pp << 1);
        const int2 lb = __ldg((const int2*)labbase + pp);

        float2 e[5];
#pragma unroll
        for (int i = 0; i < 5; i++) {
            const int c = c0 + i;
            // dead slot (c==19): exp(-100)=0 contributes nothing anywhere
            e[i] = (c < NCLS) ? __ldg((const float2*)(row + (size_t)c * HW))
                              : make_float2(-100.f, -100.f);
        }
        float Sx = 0.f, Sy = 0.f;
#pragma unroll
        for (int i = 0; i < 5; i++) {
            e[i].x = __expf(e[i].x); Sx += e[i].x;
            e[i].y = __expf(e[i].y); Sy += e[i].y;
        }
        Sx += __shfl_xor_sync(~0u, Sx, 1);  Sy += __shfl_xor_sync(~0u, Sy, 1);
        Sx += __shfl_xor_sync(~0u, Sx, 2);  Sy += __shfl_xor_sync(~0u, Sy, 2);
        // t = e*w, w = 1/(S/15).  Bin tests directly on e vs scaled thresholds.
        const float d1x = Sx * 0.0666666667f, d1y = Sy * 0.0666666667f; // t<=1
        const float d2x = d1x + d1x,          d2y = d1y + d1y;          // t<=2
        const float wx  = __fdividef(1.f, d1x);
        const float wy  = __fdividef(1.f, d1y);

#pragma unroll
        for (int i = 0; i < 5; i++) {
            const int c = c0 + i;
            {   // pixel 0: accumulate plain t (label handled per-pixel below)
                const float ev = e[i].x;
                atot[i] = fmaf(ev, wx, atot[i]);
                if (ev <= d1x) a0[i] = fmaf(ev, wx, a0[i]);
                if (ev > d2x) {                         // rare: t > 2 (~7.7%)
                    const float t = ev * wx;
                    const int bin = min(__float2int_ru(t) - 1, NBINS - 1);
                    atomicAdd(&s_hist[c * NBINS + bin], t);
                }
            }
            {   // pixel 1
                const float ev = e[i].y;
                atot[i] = fmaf(ev, wy, atot[i]);
                if (ev <= d1y) a0[i] = fmaf(ev, wy, a0[i]);
                if (ev > d2y) {
                    const float t = ev * wy;
                    const int bin = min(__float2int_ru(t) - 1, NBINS - 1);
                    atomicAdd(&s_hist[c * NBINS + bin], t);
                }
            }
        }

        // Label correction: owning lane re-reads the label logit (L1 hit),
        // rebins, and records one -15 event into the separate s_corr array.
        {
            const int dx = lb.x - c0;
            if ((unsigned)dx < 5u) {
                const float t = __expf(__ldg(row + (size_t)lb.x * HW)) * wx;
                const int bin = min(__float2int_ru(t) - 1, NBINS - 1);
                atomicAdd(&s_corr[lb.x * NBINS + max(bin, 0)], -15.f);
            }
            const int dy = lb.y - c0;
            if ((unsigned)dy < 5u) {
                const float t = __expf(__ldg(row + (size_t)lb.y * HW + 1)) * wy;
                const int bin = min(__float2int_ru(t) - 1, NBINS - 1);
                atomicAdd(&s_corr[lb.y * NBINS + max(bin, 0)], -15.f);
            }
        }
    }

    // Reduce across the 8 lanes sharing each class (xor over lane bits 2..4).
    const int lane = threadIdx.x & 31;
#pragma unroll
    for (int i = 0; i < 5; i++) {
        float x0 = atot[i], x1 = a0[i];
#pragma unroll
        for (int s = 4; s < 32; s <<= 1) {
            x0 += __shfl_xor_sync(~0u, x0, s);
            x1 += __shfl_xor_sync(~0u, x1, s);
        }
        if (lane < 4 && c0 + i < NCLS) {       // lane == its own group id
            atomicAdd(&s_tot[c0 + i], x0);
            atomicAdd(&s_b0[c0 + i],  x1);
        }
    }
    __syncthreads();

    // Flush: bin0 = b0, bin1 = tot - b0 - rare, bins>=2 = rare; + corrections.
    for (int c = threadIdx.x; c < NCLS; c += NT) {
        float rare = 0.f;
#pragma unroll
        for (int b = 2; b < NBINS; b++) rare += s_hist[c * NBINS + b];
        atomicAdd(&g_hist[c * NBINS + 0], s_b0[c] + s_corr[c * NBINS + 0]);
        atomicAdd(&g_hist[c * NBINS + 1],
                  s_tot[c] - s_b0[c] - rare + s_corr[c * NBINS + 1]);
#pragma unroll
        for (int b = 2; b < NBINS; b++) {
            const float v = s_hist[c * NBINS + b] + s_corr[c * NBINS + b];
            if (v != 0.f) atomicAdd(&g_hist[c * NBINS + b], v);
        }
    }

    // Completion protocol; last block finalizes and restores invariants.
    __threadfence();
    __syncthreads();
    if (threadIdx.x == 0) {
        const unsigned r = atomicInc(&g_count, GRIDB - 1);   // wraps back to 0
        s_last = (r == GRIDB - 1);
    }
    __syncthreads();

    if (s_last && threadIdx.x < 32) {
        __threadfence();
        double local = 0.0;
        for (int i = lane; i < NCELLS; i += 32) {
            local += fabs((double)g_hist[i]);
            g_hist[i] = 0.f;
        }
#pragma unroll
        for (int s = 16; s > 0; s >>= 1)
            local += __shfl_xor_sync(~0u, local, s);
        if (lane == 0)
            out[0] = (float)(local / (15.0 * (double)NCLS * (double)NPIX));
    }
}

extern "C" void kernel_launch(void* const* d_in, const int* in_sizes, int n_in,
                              void* d_out, int out_size) {
    const float* logits;
    const int*   labels;
    if (in_sizes[0] == NPIX) {               // defensive order detection by size
        labels = (const int*)d_in[0];
        logits = (const float*)d_in[1];
    } else {
        logits = (const float*)d_in[0];
        labels = (const int*)d_in[1];
    }
    float* out = (float*)d_out;

    dim3 grid(GX, 4);
    ece_fused<<<grid, NT>>>(logits, labels, out);
}

// round 12
// speedup vs baseline: 1.1598x; 1.0587x over previous
#include <cuda_runtime.h>

#define NCLS    19
#define NBINS   15
#define HW      (512 * 1024)          // 2^19 pixels per image
#define NPIX    (4 * HW)              // 2,097,152
#define HPAIR   (HW / 2)              // 262,144 pairs per image
#define NCELLS  (NCLS * NBINS)        // 285
#define NT      512
#define GX      111                   // blocks per image; 111*4 = 444 = 3/SM
#define GRIDB   (GX * 4)
#define PPB     (NT / 4)              // 128 pairs per block-iteration
#define STRIDE  (GX * PPB)            // 14,208 pairs

// g_hist[c*15+b] = sum of 15*(p - [label==c]) over pixels with bin(p_c)=b.
// sce = sum(|g_hist|) / (15*C*N).  Invariant: zero at entry; last block resets.
__device__ float    g_hist[NCELLS];
__device__ unsigned g_count;

__global__ __launch_bounds__(NT, 3)
void ece_fused(const float* __restrict__ logits,
               const int*   __restrict__ labels,
               float*       __restrict__ out) {
    __shared__ float s_hist[NCELLS];   // rare v-sums, bins >= 2 only
    __shared__ float s_b0[NCLS];       // per-class sum of v over t<=1
    __shared__ float s_tot[NCLS];      // per-class total sum of v
    __shared__ bool  s_last;
    for (int i = threadIdx.x; i < NCELLS; i += NT) s_hist[i] = 0.f;
    if (threadIdx.x < NCLS) { s_b0[threadIdx.x] = 0.f; s_tot[threadIdx.x] = 0.f; }
    __syncthreads();

    const int g  = threadIdx.x & 3;        // class group within pixel quad
    const int q  = threadIdx.x >> 2;       // pair slot within block
    const int c0 = g * 5;                  // first owned class (g=3 owns 4)

    const float* imgbase = logits + (size_t)blockIdx.y * (NCLS * HW);
    const int*   labbase = labels + (size_t)blockIdx.y * HW;

    float a0[5], atot[5];
#pragma unroll
    for (int i = 0; i < 5; i++) { a0[i] = 0.f; atot[i] = 0.f; }

    for (unsigned pp = blockIdx.x * PPB + q; pp < HPAIR; pp += STRIDE) {
        const float* row = imgbase + (pp << 1);
        const int2 lb = __ldg((const int2*)labbase + pp);

        float2 e[5];
#pragma unroll
        for (int i = 0; i < 5; i++) {
            const int c = c0 + i;
            // dead slot (c==19): exp(-100)=0 contributes nothing anywhere
            e[i] = (c < NCLS) ? __ldg((const float2*)(row + (size_t)c * HW))
                              : make_float2(-100.f, -100.f);
        }
        float Sx = 0.f, Sy = 0.f;
#pragma unroll
        for (int i = 0; i < 5; i++) {
            e[i].x = __expf(e[i].x); Sx += e[i].x;
            e[i].y = __expf(e[i].y); Sy += e[i].y;
        }
        Sx += __shfl_xor_sync(~0u, Sx, 1);  Sy += __shfl_xor_sync(~0u, Sy, 1);
        Sx += __shfl_xor_sync(~0u, Sx, 2);  Sy += __shfl_xor_sync(~0u, Sy, 2);
        const float wx = __fdividef(15.f, Sx);
        const float wy = __fdividef(15.f, Sy);

#pragma unroll
        for (int i = 0; i < 5; i++) {
            const int c = c0 + i;
            {   // pixel 0
                const float t = e[i].x * wx;                 // 15*p
                const float v = (c == lb.x) ? t - 15.f : t;  // 15*(p - eq)
                atot[i] += v;                                // unconditional total
                if (t <= 1.f) a0[i] += v;                    // predicated add
                if (t > 2.f) {                               // rare (~7.7%), branchy
                    const int bin = min(__float2int_ru(t) - 1, NBINS - 1);
                    atomicAdd(&s_hist[c * NBINS + bin], v);
                }
            }
            {   // pixel 1
                const float t = e[i].y * wy;
                const float v = (c == lb.y) ? t - 15.f : t;
                atot[i] += v;
                if (t <= 1.f) a0[i] += v;
                if (t > 2.f) {
                    const int bin = min(__float2int_ru(t) - 1, NBINS - 1);
                    atomicAdd(&s_hist[c * NBINS + bin], v);
                }
            }
        }
    }

    // Reduce across the 8 lanes sharing each class (xor over lane bits 2..4).
    const int lane = threadIdx.x & 31;
#pragma unroll
    for (int i = 0; i < 5; i++) {
        float x0 = atot[i], x1 = a0[i];
#pragma unroll
        for (int s = 4; s < 32; s <<= 1) {
            x0 += __shfl_xor_sync(~0u, x0, s);
            x1 += __shfl_xor_sync(~0u, x1, s);
        }
        if (lane < 4 && c0 + i < NCLS) {       // lane == its own group id
            atomicAdd(&s_tot[c0 + i], x0);
            atomicAdd(&s_b0[c0 + i],  x1);
        }
    }
    __syncthreads();

    // Flush: bin0 = b0, bin1 = tot - b0 - rare, bins>=2 = rare cells.
    for (int c = threadIdx.x; c < NCLS; c += NT) {
        float rare = 0.f;
#pragma unroll
        for (int b = 2; b < NBINS; b++) rare += s_hist[c * NBINS + b];
        atomicAdd(&g_hist[c * NBINS + 0], s_b0[c]);
        atomicAdd(&g_hist[c * NBINS + 1], s_tot[c] - s_b0[c] - rare);
#pragma unroll
        for (int b = 2; b < NBINS; b++) {
            const float v = s_hist[c * NBINS + b];
            if (v != 0.f) atomicAdd(&g_hist[c * NBINS + b], v);
        }
    }

    // Completion protocol; last block finalizes and restores invariants.
    __threadfence();
    __syncthreads();
    if (threadIdx.x == 0) {
        const unsigned r = atomicInc(&g_count, GRIDB - 1);   // wraps back to 0
        s_last = (r == GRIDB - 1);
    }
    __syncthreads();

    if (s_last && threadIdx.x < 32) {
        __threadfence();
        double local = 0.0;
        for (int i = lane; i < NCELLS; i += 32) {
            local += fabs((double)g_hist[i]);
            g_hist[i] = 0.f;
        }
#pragma unroll
        for (int s = 16; s > 0; s >>= 1)
            local += __shfl_xor_sync(~0u, local, s);
        if (lane == 0)
            out[0] = (float)(local / (15.0 * (double)NCLS * (double)NPIX));
    }
}

extern "C" void kernel_launch(void* const* d_in, const int* in_sizes, int n_in,
                              void* d_out, int out_size) {
    const float* logits;
    const int*   labels;
    if (in_sizes[0] == NPIX) {               // defensive order detection by size
        labels = (const int*)d_in[0];
        logits = (const float*)d_in[1];
    } else {
        logits = (const float*)d_in[0];
        labels = (const int*)d_in[1];
    }
    float* out = (float*)d_out;

    dim3 grid(GX, 4);
    ece_fused<<<grid, NT>>>(logits, labels, out);
}

// round 13
// speedup vs baseline: 1.3637x; 1.1758x over previous
#include <cuda_runtime.h>

#define NCLS    19
#define NBINS   15
#define HW      (512 * 1024)          // 2^19
#define NPIX    (4 * HW)              // 2,097,152
#define NCELLS  (NCLS * NBINS)        // 285
#define NT      512
#define GRIDB   444                   // 3 blocks/SM on 148 SMs
#define PPB     (NT / 4)              // 128 pixels per block-iteration
#define STRIDE  (GRIDB * PPB)

// g_hist[c*15+b] = sum of 15*(p - [label==c]) over pixels with bin(p_c)=b.
// sce = sum(|g_hist|) / (15*C*N).  Invariant: zero at entry; last block resets.
__device__ float    g_hist[NCELLS];
__device__ unsigned g_count;

__global__ __launch_bounds__(NT, 3)
void ece_fused(const float* __restrict__ logits,
               const int*   __restrict__ labels,
               float*       __restrict__ out) {
    __shared__ float s_hist[NCELLS];
    __shared__ bool  s_last;
    for (int i = threadIdx.x; i < NCELLS; i += NT) s_hist[i] = 0.f;
    __syncthreads();

    const unsigned sbase = (unsigned)__cvta_generic_to_shared(s_hist);
    const int g  = threadIdx.x & 3;       // class-group within the pixel quad
    const int q  = threadIdx.x >> 2;      // pixel slot within block
    const int c0 = g * 5;                 // first class of this group (g=3 has 4)

    // Cumulative register bins per owned class: a0 = sum v over t<=1, a1 over t<=2.
    float a0[5], a1[5];
#pragma unroll
    for (int i = 0; i < 5; i++) { a0[i] = 0.f; a1[i] = 0.f; }

    for (unsigned p = blockIdx.x * PPB + q; p < NPIX; p += STRIDE) {
        const unsigned b  = p >> 19;
        const unsigned hw = p & (HW - 1);
        const float* row  = logits + (size_t)b * (NCLS * HW) + hw;
        const int lab = __ldg(labels + p);          // broadcast within quad

        float e[5];
#pragma unroll
        for (int i = 0; i < 5; i++) {
            const int c = c0 + i;
            // dead slot (c==19) -> exp(-100)=0: contributes nothing anywhere
            e[i] = (c < NCLS) ? __ldg(row + (size_t)c * HW) : -100.f;
        }
        float S = 0.f;
#pragma unroll
        for (int i = 0; i < 5; i++) { e[i] = __expf(e[i]); S += e[i]; }
        // Softmax denominator across the 4-lane quad: two butterflies.
        S += __shfl_xor_sync(~0u, S, 1);
        S += __shfl_xor_sync(~0u, S, 2);
        const float w = __fdividef(15.f, S);

#pragma unroll
        for (int i = 0; i < 5; i++) {
            const int c = c0 + i;
            const float t = e[i] * w;               // 15*p  (0 for dead slot)
            float v = t;
            if (c == lab) v = t - 15.f;             // predicated label adjust
            if (t <= 1.f) a0[i] += v;               // cumulative levels
            if (t <= 2.f) a1[i] += v;
            // Rare path (t > 2, ~7.7%): branch-free predicated shared red.
            // cell = c*15 + (min(ceil(t),15) - 1); in-bounds for all t >= 0.
            const unsigned addr = sbase +
                (unsigned)((c * NBINS - 1 + min(__float2int_ru(t), NBINS)) << 2);
            // volatile, NO memory clobber: reds are independent accumulations,
            // drained by the __syncthreads() before the flush below.
            asm volatile(
                "{ .reg .pred p; setp.gt.f32 p, %1, 0f40000000;\n\t"
                "  @p red.shared.add.f32 [%0], %2; }"
                :: "r"(addr), "f"(t), "f"(v));
        }
    }

    // Reduce accumulators over lanes of the same group (bits 2..4 of lane id).
    const int lane = threadIdx.x & 31;
#pragma unroll
    for (int i = 0; i < 5; i++) {
        float x0 = a0[i], x1 = a1[i];
#pragma unroll
        for (int s = 4; s < 32; s <<= 1) {
            x0 += __shfl_xor_sync(~0u, x0, s);
            x1 += __shfl_xor_sync(~0u, x1, s);
        }
        if (lane < 4 && c0 + i < NCLS) {            // lane == its own group id
            atomicAdd(&s_hist[(c0 + i) * NBINS + 0], x0);
            atomicAdd(&s_hist[(c0 + i) * NBINS + 1], x1 - x0);
        }
    }
    __syncthreads();

    for (int i = threadIdx.x; i < NCELLS; i += NT) {
        const float v = s_hist[i];
        if (v != 0.f) atomicAdd(&g_hist[i], v);
    }

    // Completion protocol; last block finalizes and restores invariants.
    __threadfence();
    __syncthreads();
    if (threadIdx.x == 0) {
        const unsigned r = atomicInc(&g_count, GRIDB - 1);   // wraps back to 0
        s_last = (r == GRIDB - 1);
    }
    __syncthreads();

    if (s_last && threadIdx.x < 32) {
        __threadfence();
        double local = 0.0;
        for (int i = lane; i < NCELLS; i += 32) {
            local += fabs((double)g_hist[i]);
            g_hist[i] = 0.f;
        }
#pragma unroll
        for (int s = 16; s > 0; s >>= 1)
            local += __shfl_xor_sync(~0u, local, s);
        if (lane == 0)
            out[0] = (float)(local / (15.0 * (double)NCLS * (double)NPIX));
    }
}

extern "C" void kernel_launch(void* const* d_in, const int* in_sizes, int n_in,
                              void* d_out, int out_size) {
    const float* logits;
    const int*   labels;
    if (in_sizes[0] == NPIX) {               // defensive order detection by size
        labels = (const int*)d_in[0];
        logits = (const float*)d_in[1];
    } else {
        logits = (const float*)d_in[0];
        labels = (const int*)d_in[1];
    }
    float* out = (float*)d_out;

    ece_fused<<<GRIDB, NT>>>(logits, labels, out);
}